// round 11
// baseline (speedup 1.0000x reference)
#include <cuda_runtime.h>
#include <cuda_bf16.h>
#include <cstdint>

#define NFIELD 39
#define VOCAB  200000
#define BATCH  16384
#define ROWSPB 64
#define THREADS 128
#define NCHUNK 10          // 10 chunks x 4 fields (kstep16) = 640 padded k

// B fragments, chunk-major: [chunk10][hl2][s4][tp4][lane32][4 u32] = 160KB
__device__ __align__(16) uint32_t BfragG[10 * 2 * 4 * 4 * 32 * 4];

__global__ void prep_kernel(const float* __restrict__ W1, const float* __restrict__ Wi) {
    int i = blockIdx.x * blockDim.x + threadIdx.x;
    if (i >= 10 * 2 * 4 * 4 * 32 * 4) return;
    int reg = i & 3;
    int l   = (i >> 2) & 31;
    int tp  = (i >> 7) & 3;
    int s   = (i >> 9) & 3;
    int hl  = (i >> 11) & 1;
    int c   = i >> 12;
    int gs = c * 4 + s;
    int t  = tp * 2 + (reg >> 1);
    int n  = t * 8 + (l >> 2);
    int k0 = gs * 16 + (l & 3) * 2 + (reg & 1) * 8;
    float v0 = 0.f, v1 = 0.f;
    if (k0 < 624)     v0 = (n < 32) ? W1[n * 624 + k0]     : Wi[(n - 32) * 624 + k0];
    if (k0 + 1 < 624) v1 = (n < 32) ? W1[n * 624 + k0 + 1] : Wi[(n - 32) * 624 + k0 + 1];
    float h0 = __bfloat162float(__float2bfloat16(v0));
    float h1 = __bfloat162float(__float2bfloat16(v1));
    uint32_t w;
    if (hl == 0) {
        asm("cvt.rn.bf16x2.f32 %0, %1, %2;" : "=r"(w) : "f"(h1), "f"(h0));
    } else {
        float r0 = v0 - h0, r1 = v1 - h1;
        asm("cvt.rn.bf16x2.f32 %0, %1, %2;" : "=r"(w) : "f"(r1), "f"(r0));
    }
    BfragG[i] = w;
}

__device__ __forceinline__ uint32_t packbf(float lo_elem, float hi_elem) {
    uint32_t r;
    asm("cvt.rn.bf16x2.f32 %0, %1, %2;" : "=r"(r) : "f"(hi_elem), "f"(lo_elem));
    return r;
}
__device__ __forceinline__ void mma16816(float* d, uint32_t a0, uint32_t a1, uint32_t a2, uint32_t a3,
                                         uint32_t b0, uint32_t b1) {
    asm volatile("mma.sync.aligned.m16n8k16.row.col.f32.bf16.bf16.f32 "
                 "{%0,%1,%2,%3}, {%4,%5,%6,%7}, {%8,%9}, {%0,%1,%2,%3};"
                 : "+f"(d[0]), "+f"(d[1]), "+f"(d[2]), "+f"(d[3])
                 : "r"(a0), "r"(a1), "r"(a2), "r"(a3), "r"(b0), "r"(b1));
}
__device__ __forceinline__ void ldsm4(uint32_t& r0, uint32_t& r1, uint32_t& r2, uint32_t& r3,
                                      uint32_t addr) {
    asm volatile("ldmatrix.sync.aligned.m8n8.x4.shared.b16 {%0,%1,%2,%3}, [%4];"
                 : "=r"(r0), "=r"(r1), "=r"(r2), "=r"(r3) : "r"(addr));
}
__device__ __forceinline__ void pair_bar(int id) {
    asm volatile("bar.sync %0, %1;" :: "r"(id), "r"(64) : "memory");
}

// smem (32KB): A only: [pair2][buf2][hl2][s4][m2 x 512B]  (pair stride 16KB, buf 8KB)
#define SMEM_BYTES 32768
// epilogue aliases (3-buffer scheme fits 32KB):
#define EXP_FO 0        // 64 x 33 floats  (8448 B)  -> later h1
#define EXP_S  8448     // 64 x 33 floats             -> later h2
#define EXP_M  16896    // MLP weights (2145 floats, 8580 B)

__global__ __launch_bounds__(THREADS, 2)
void pnn_kernel(const int*   __restrict__ Xi,
                const float* __restrict__ Xv,
                const float* __restrict__ tables,
                const float* __restrict__ lin1_w,
                const float* __restrict__ lin1_b,
                const float* __restrict__ lin2_w,
                const float* __restrict__ lin2_b,
                const float* __restrict__ last_w,
                const float* __restrict__ last_b,
                float*       __restrict__ out) {
    extern __shared__ unsigned char smem[];
    const uint32_t sbase = (uint32_t)__cvta_generic_to_shared(smem);

    const int tid = threadIdx.x;
    const int wid = tid >> 5;
    const int l   = tid & 31;
    const int b0  = blockIdx.x * ROWSPB;

    // MMA mapping: pair p owns rows [p*32, p*32+32); nh selects cols [nh*32, +32)
    const int p  = wid >> 1;         // 0..1
    const int nh = wid & 1;
    const uint32_t apair = (uint32_t)(p * 16384);

    // gather mapping (pair-private): 64 threads; quad = (row_local, field) item
    const int pt = tid & 63;
    const int qi = pt >> 2;          // 0..15
    const int q  = pt & 3;           // 16B segment of 64B embedding row

    int    nidx[3][8];
    float  nxv[3][8];
    float4 tdat[2][8];

    float acc[2][4][4];              // [m][local ntile][reg]
    #pragma unroll
    for (int m = 0; m < 2; ++m)
        #pragma unroll
        for (int t = 0; t < 4; ++t)
            #pragma unroll
            for (int r = 0; r < 4; ++r) acc[m][t][r] = 0.f;

    const uint4* __restrict__ Bp = (const uint4*)BfragG;

    auto load_idx = [&](int c, int slot) {
        #pragma unroll
        for (int it = 0; it < 8; ++it) {
            int rl = (it >> 2) * 16 + qi;
            int f  = c * 4 + (it & 3);
            int row = b0 + p * 32 + rl;
            if (f < NFIELD) {
                nidx[slot][it] = Xi[(size_t)row * NFIELD + f];
                nxv[slot][it]  = Xv[(size_t)row * NFIELD + f];
            } else {
                nidx[slot][it] = 0;
                nxv[slot][it]  = 0.f;
            }
        }
    };
    auto table_ldg = [&](int c) {
        const int islot = c % 3, tslot = c & 1;
        #pragma unroll
        for (int it = 0; it < 8; ++it) {
            int f = c * 4 + (it & 3);
            if (f < NFIELD)
                tdat[tslot][it] = __ldcg(((const float4*)tables) + ((long)f * VOCAB + nidx[islot][it]) * 4 + q);
            else
                tdat[tslot][it] = make_float4(0.f, 0.f, 0.f, 0.f);
        }
    };
    auto cv_store = [&](int c) {
        const int islot = c % 3, tslot = c & 1;
        const uint32_t bufo = apair + (uint32_t)((c & 1) * 8192);
        #pragma unroll
        for (int it = 0; it < 8; ++it) {
            int rl = (it >> 2) * 16 + qi;
            int j  = it & 3;
            float xv = nxv[islot][it];
            float4 t4 = tdat[tslot][it];
            float v0 = t4.x * xv, v1 = t4.y * xv, v2 = t4.z * xv, v3 = t4.w * xv;
            float r0 = v0 - __bfloat162float(__float2bfloat16(v0));
            float r1 = v1 - __bfloat162float(__float2bfloat16(v1));
            float r2 = v2 - __bfloat162float(__float2bfloat16(v2));
            float r3 = v3 - __bfloat162float(__float2bfloat16(v3));
            uint32_t inoff = (uint32_t)((rl >> 4) * 512 + (q >> 1) * 256 + (rl & 15) * 16 + (q & 1) * 8);
            unsigned char* bh = smem + bufo + (0 * 4 + j) * 1024 + inoff;
            unsigned char* bl = smem + bufo + (4 + j) * 1024 + inoff;
            *(uint2*)bh = make_uint2(packbf(v0, v1), packbf(v2, v3));
            *(uint2*)bl = make_uint2(packbf(r0, r1), packbf(r2, r3));
        }
    };
    auto do_mma = [&](int c) {
        const uint32_t abase = sbase + apair + (uint32_t)((c & 1) * 8192);
        const uint32_t laddr = (uint32_t)((l & 15) * 16 + (l >> 4) * 256);
        #pragma unroll
        for (int s = 0; s < 4; ++s) {
            // B frags straight from global (L1-resident; gathers bypass via .cg)
            uint4 Bh0 = Bp[c * 1024 + 0 * 512 + s * 128 + (nh * 2 + 0) * 32 + l];
            uint4 Bh1 = Bp[c * 1024 + 0 * 512 + s * 128 + (nh * 2 + 1) * 32 + l];
            uint4 Bl0 = Bp[c * 1024 + 1 * 512 + s * 128 + (nh * 2 + 0) * 32 + l];
            uint4 Bl1 = Bp[c * 1024 + 1 * 512 + s * 128 + (nh * 2 + 1) * 32 + l];
            #pragma unroll
            for (int m = 0; m < 2; ++m) {
                uint32_t ah0, ah1, ah2, ah3, al0, al1, al2, al3;
                ldsm4(ah0, ah1, ah2, ah3, abase + (0 * 4 + s) * 1024 + m * 512 + laddr);
                ldsm4(al0, al1, al2, al3, abase + (4 + s) * 1024 + m * 512 + laddr);
                mma16816(acc[m][0], ah0, ah1, ah2, ah3, Bh0.x, Bh0.y);
                mma16816(acc[m][1], ah0, ah1, ah2, ah3, Bh0.z, Bh0.w);
                mma16816(acc[m][2], ah0, ah1, ah2, ah3, Bh1.x, Bh1.y);
                mma16816(acc[m][3], ah0, ah1, ah2, ah3, Bh1.z, Bh1.w);
                mma16816(acc[m][0], ah0, ah1, ah2, ah3, Bl0.x, Bl0.y);
                mma16816(acc[m][1], ah0, ah1, ah2, ah3, Bl0.z, Bl0.w);
                mma16816(acc[m][2], ah0, ah1, ah2, ah3, Bl1.x, Bl1.y);
                mma16816(acc[m][3], ah0, ah1, ah2, ah3, Bl1.z, Bl1.w);
                mma16816(acc[m][0], al0, al1, al2, al3, Bh0.x, Bh0.y);
                mma16816(acc[m][1], al0, al1, al2, al3, Bh0.z, Bh0.w);
                mma16816(acc[m][2], al0, al1, al2, al3, Bh1.x, Bh1.y);
                mma16816(acc[m][3], al0, al1, al2, al3, Bh1.z, Bh1.w);
            }
        }
    };

    // ---- prologue ----
    load_idx(0, 0);
    load_idx(1, 1);
    load_idx(2, 2);
    table_ldg(0);
    table_ldg(1);
    cv_store(0);
    pair_bar(p + 1);

    // ---- free-running pipelined loop (pair-local sync only) ----
    #pragma unroll
    for (int c = 0; c < NCHUNK; ++c) {
        if (c + 3 < NCHUNK) load_idx(c + 3, (c + 3) % 3);
        if (c + 2 < NCHUNK) table_ldg(c + 2);
        do_mma(c);
        if (c + 1 < NCHUNK) cv_store(c + 1);
        if (c + 1 < NCHUNK) pair_bar(p + 1);
    }
    __syncthreads();

    // ---- epilogue (3 buffers inside the 32KB A region) ----
    float* sFO = (float*)(smem + EXP_FO);
    float* sS  = (float*)(smem + EXP_S);
    float* sM  = (float*)(smem + EXP_M);

    {
        float* dst = nh ? sS : sFO;
        #pragma unroll
        for (int m = 0; m < 2; ++m) {
            const int r0 = p * 32 + m * 16 + (l >> 2);
            const int r1 = r0 + 8;
            #pragma unroll
            for (int t = 0; t < 4; ++t) {
                const int c0 = t * 8 + (l & 3) * 2;
                dst[r0 * 33 + c0]     = acc[m][t][0];
                dst[r0 * 33 + c0 + 1] = acc[m][t][1];
                dst[r1 * 33 + c0]     = acc[m][t][2];
                dst[r1 * 33 + c0 + 1] = acc[m][t][3];
            }
        }
    }
    for (int i = tid; i < 1024; i += THREADS) {
        sM[i]        = lin1_w[i];
        sM[1056 + i] = lin2_w[i];
    }
    if (tid < 32) {
        sM[1024 + tid] = lin1_b[tid];
        sM[2080 + tid] = lin2_b[tid];
        sM[2112 + tid] = last_w[tid];
    }
    if (tid == 0) sM[2144] = last_b[0];
    __syncthreads();

    // ---- MLP: 2 threads per row, 16 outputs each ----
    const int mrow = tid >> 1;       // 0..63
    const int mh   = tid & 1;

    float xr[32];
    #pragma unroll
    for (int j = 0; j < 32; ++j) {
        float s = sS[mrow * 33 + j];
        xr[j] = fmaf(s, s, sFO[mrow * 33 + j]);
    }
    __syncthreads();                 // all reads of sFO/sS done before overwrite

    #pragma unroll
    for (int i = 0; i < 16; ++i) {
        int oi = mh * 16 + i;
        float t = sM[1024 + oi];
        #pragma unroll
        for (int j4 = 0; j4 < 8; ++j4) {
            float4 w = *(const float4*)&sM[oi * 32 + j4 * 4];
            t = fmaf(xr[j4 * 4],     w.x, t);
            t = fmaf(xr[j4 * 4 + 1], w.y, t);
            t = fmaf(xr[j4 * 4 + 2], w.z, t);
            t = fmaf(xr[j4 * 4 + 3], w.w, t);
        }
        sFO[mrow * 33 + oi] = fmaxf(t, 0.f);     // h1 overwrites sFO
    }
    __syncthreads();

    float hr[32];
    #pragma unroll
    for (int j = 0; j < 32; ++j) hr[j] = sFO[mrow * 33 + j];
    #pragma unroll
    for (int i = 0; i < 16; ++i) {
        int oi = mh * 16 + i;
        float t = sM[2080 + oi];
        #pragma unroll
        for (int j4 = 0; j4 < 8; ++j4) {
            float4 w = *(const float4*)&sM[1056 + oi * 32 + j4 * 4];
            t = fmaf(hr[j4 * 4],     w.x, t);
            t = fmaf(hr[j4 * 4 + 1], w.y, t);
            t = fmaf(hr[j4 * 4 + 2], w.z, t);
            t = fmaf(hr[j4 * 4 + 3], w.w, t);
        }
        sS[mrow * 33 + oi] = fmaxf(t, 0.f);      // h2 overwrites sS
    }
    __syncthreads();

    if (mh == 0) {
        float o = sM[2144];
        #pragma unroll
        for (int j = 0; j < 32; ++j) o = fmaf(sS[mrow * 33 + j], sM[2112 + j], o);
        out[b0 + mrow] = o;
    }
}

extern "C" void kernel_launch(void* const* d_in, const int* in_sizes, int n_in,
                              void* d_out, int out_size) {
    const int*   Xi     = (const int*)  d_in[0];
    const float* Xv     = (const float*)d_in[1];
    const float* tables = (const float*)d_in[2];
    const float* W1     = (const float*)d_in[3];
    const float* Wi     = (const float*)d_in[4];
    const float* lin1_w = (const float*)d_in[5];
    const float* lin1_b = (const float*)d_in[6];
    const float* lin2_w = (const float*)d_in[7];
    const float* lin2_b = (const float*)d_in[8];
    const float* last_w = (const float*)d_in[9];
    const float* last_b = (const float*)d_in[10];
    float* out = (float*)d_out;

    static bool attr_set = false;
    if (!attr_set) {
        cudaFuncSetAttribute(pnn_kernel, cudaFuncAttributeMaxDynamicSharedMemorySize, SMEM_BYTES);
        attr_set = true;
    }

    prep_kernel<<<(10 * 2 * 4 * 4 * 32 * 4 + 255) / 256, 256>>>(W1, Wi);
    pnn_kernel<<<BATCH / ROWSPB, THREADS, SMEM_BYTES>>>(
        Xi, Xv, tables, lin1_w, lin1_b, lin2_w, lin2_b, last_w, last_b, out);
}

// round 12
// speedup vs baseline: 1.0620x; 1.0620x over previous
#include <cuda_runtime.h>
#include <cuda_bf16.h>
#include <cstdint>

#define NFIELD 39
#define VOCAB  200000
#define BATCH  16384
#define ROWSPB 128
#define THREADS 256
#define NCHUNK 10          // 10 chunks x 4 fields (kstep16) = 640 padded k

// B fragments, chunk-major: [chunk10][hl2][s4][tp4][lane32][4 u32] = 160KB
__device__ __align__(16) uint32_t BfragG[10 * 2 * 4 * 4 * 32 * 4];

__global__ void prep_kernel(const float* __restrict__ W1, const float* __restrict__ Wi) {
    int i = blockIdx.x * blockDim.x + threadIdx.x;
    if (i >= 10 * 2 * 4 * 4 * 32 * 4) return;
    int reg = i & 3;
    int l   = (i >> 2) & 31;
    int tp  = (i >> 7) & 3;
    int s   = (i >> 9) & 3;
    int hl  = (i >> 11) & 1;
    int c   = i >> 12;
    int gs = c * 4 + s;
    int t  = tp * 2 + (reg >> 1);
    int n  = t * 8 + (l >> 2);
    int k0 = gs * 16 + (l & 3) * 2 + (reg & 1) * 8;
    float v0 = 0.f, v1 = 0.f;
    if (k0 < 624)     v0 = (n < 32) ? W1[n * 624 + k0]     : Wi[(n - 32) * 624 + k0];
    if (k0 + 1 < 624) v1 = (n < 32) ? W1[n * 624 + k0 + 1] : Wi[(n - 32) * 624 + k0 + 1];
    float h0 = __bfloat162float(__float2bfloat16(v0));
    float h1 = __bfloat162float(__float2bfloat16(v1));
    uint32_t w;
    if (hl == 0) {
        asm("cvt.rn.bf16x2.f32 %0, %1, %2;" : "=r"(w) : "f"(h1), "f"(h0));
    } else {
        float r0 = v0 - h0, r1 = v1 - h1;
        asm("cvt.rn.bf16x2.f32 %0, %1, %2;" : "=r"(w) : "f"(r1), "f"(r0));
    }
    BfragG[i] = w;
}

__device__ __forceinline__ uint32_t packbf(float lo_elem, float hi_elem) {
    uint32_t r;
    asm("cvt.rn.bf16x2.f32 %0, %1, %2;" : "=r"(r) : "f"(hi_elem), "f"(lo_elem));
    return r;
}
__device__ __forceinline__ void mma16816(float* d, uint32_t a0, uint32_t a1, uint32_t a2, uint32_t a3,
                                         uint32_t b0, uint32_t b1) {
    asm volatile("mma.sync.aligned.m16n8k16.row.col.f32.bf16.bf16.f32 "
                 "{%0,%1,%2,%3}, {%4,%5,%6,%7}, {%8,%9}, {%0,%1,%2,%3};"
                 : "+f"(d[0]), "+f"(d[1]), "+f"(d[2]), "+f"(d[3])
                 : "r"(a0), "r"(a1), "r"(a2), "r"(a3), "r"(b0), "r"(b1));
}
__device__ __forceinline__ void ldsm4(uint32_t& r0, uint32_t& r1, uint32_t& r2, uint32_t& r3,
                                      uint32_t addr) {
    asm volatile("ldmatrix.sync.aligned.m8n8.x4.shared.b16 {%0,%1,%2,%3}, [%4];"
                 : "=r"(r0), "=r"(r1), "=r"(r2), "=r"(r3) : "r"(addr));
}
__device__ __forceinline__ void pair_bar(int id) {
    asm volatile("bar.sync %0, %1;" :: "r"(id), "r"(64) : "memory");
}

// smem (64KB): A only: [pair4][buf2][hl2][s4][m2 x 512B]  (pair stride 16KB, buf 8KB)
#define SMEM_BYTES 65536
// epilogue aliases (all warps done with A by then):
#define EXP_FO 0        // 128 x 33 floats
#define EXP_S  16896
#define EXP_M  33792    // MLP weights (2145 floats)
#define EXP_H  42384

__global__ __launch_bounds__(THREADS, 1)
void pnn_kernel(const int*   __restrict__ Xi,
                const float* __restrict__ Xv,
                const float* __restrict__ tables,
                const float* __restrict__ lin1_w,
                const float* __restrict__ lin1_b,
                const float* __restrict__ lin2_w,
                const float* __restrict__ lin2_b,
                const float* __restrict__ last_w,
                const float* __restrict__ last_b,
                float*       __restrict__ out) {
    extern __shared__ unsigned char smem[];
    const uint32_t sbase = (uint32_t)__cvta_generic_to_shared(smem);

    const int tid = threadIdx.x;
    const int wid = tid >> 5;
    const int l   = tid & 31;
    const int b0  = blockIdx.x * ROWSPB;

    // MMA mapping: pair p owns rows [p*32, p*32+32); nh selects cols [nh*32, +32)
    const int p  = wid >> 1;
    const int nh = wid & 1;
    const uint32_t apair = (uint32_t)(p * 16384);

    // gather mapping (pair-private): 64 threads; quad = (row_local, field) item
    const int pt = tid & 63;
    const int qi = pt >> 2;          // 0..15
    const int q  = pt & 3;           // 16B segment of 64B embedding row

    int    nidx[3][8];
    float  nxv[3][8];
    float4 tdat[2][8];
    uint4  Breg[2][4];               // double-buffered B fragments

    float acc[2][4][4];              // [m][local ntile][reg]
    #pragma unroll
    for (int m = 0; m < 2; ++m)
        #pragma unroll
        for (int t = 0; t < 4; ++t)
            #pragma unroll
            for (int r = 0; r < 4; ++r) acc[m][t][r] = 0.f;

    const uint4* __restrict__ Bp = (const uint4*)BfragG;

    auto bload = [&](int c, int s, int par) {
        Breg[par][0] = Bp[c * 1024 + 0 * 512 + s * 128 + (nh * 2 + 0) * 32 + l];
        Breg[par][1] = Bp[c * 1024 + 0 * 512 + s * 128 + (nh * 2 + 1) * 32 + l];
        Breg[par][2] = Bp[c * 1024 + 1 * 512 + s * 128 + (nh * 2 + 0) * 32 + l];
        Breg[par][3] = Bp[c * 1024 + 1 * 512 + s * 128 + (nh * 2 + 1) * 32 + l];
    };
    auto load_idx = [&](int c, int slot) {
        #pragma unroll
        for (int it = 0; it < 8; ++it) {
            int rl = (it >> 2) * 16 + qi;
            int f  = c * 4 + (it & 3);
            int row = b0 + p * 32 + rl;
            if (f < NFIELD) {
                nidx[slot][it] = Xi[(size_t)row * NFIELD + f];
                nxv[slot][it]  = Xv[(size_t)row * NFIELD + f];
            } else {
                nidx[slot][it] = 0;
                nxv[slot][it]  = 0.f;
            }
        }
    };
    auto table_ldg = [&](int c) {
        const int islot = c % 3, tslot = c & 1;
        #pragma unroll
        for (int it = 0; it < 8; ++it) {
            int f = c * 4 + (it & 3);
            if (f < NFIELD)   // .cg: keep gather stream out of L1 so B stays resident
                tdat[tslot][it] = __ldcg(((const float4*)tables) + ((long)f * VOCAB + nidx[islot][it]) * 4 + q);
            else
                tdat[tslot][it] = make_float4(0.f, 0.f, 0.f, 0.f);
        }
    };
    auto cv_store = [&](int c) {
        const int islot = c % 3, tslot = c & 1;
        const uint32_t bufo = apair + (uint32_t)((c & 1) * 8192);
        #pragma unroll
        for (int it = 0; it < 8; ++it) {
            int rl = (it >> 2) * 16 + qi;
            int j  = it & 3;
            float xv = nxv[islot][it];
            float4 t4 = tdat[tslot][it];
            float v0 = t4.x * xv, v1 = t4.y * xv, v2 = t4.z * xv, v3 = t4.w * xv;
            float r0 = v0 - __bfloat162float(__float2bfloat16(v0));
            float r1 = v1 - __bfloat162float(__float2bfloat16(v1));
            float r2 = v2 - __bfloat162float(__float2bfloat16(v2));
            float r3 = v3 - __bfloat162float(__float2bfloat16(v3));
            uint32_t inoff = (uint32_t)((rl >> 4) * 512 + (q >> 1) * 256 + (rl & 15) * 16 + (q & 1) * 8);
            unsigned char* bh = smem + bufo + (0 * 4 + j) * 1024 + inoff;
            unsigned char* bl = smem + bufo + (4 + j) * 1024 + inoff;
            *(uint2*)bh = make_uint2(packbf(v0, v1), packbf(v2, v3));
            *(uint2*)bl = make_uint2(packbf(r0, r1), packbf(r2, r3));
        }
    };
    auto do_mma = [&](int c) {
        const uint32_t abase = sbase + apair + (uint32_t)((c & 1) * 8192);
        const uint32_t laddr = (uint32_t)((l & 15) * 16 + (l >> 4) * 256);
        #pragma unroll
        for (int s = 0; s < 4; ++s) {
            const int cur = s & 1, nxt = cur ^ 1;
            // issue next B loads first: consumed one s-step (>=100cyc) later
            if (s < 3)                 bload(c, s + 1, nxt);
            else if (c + 1 < NCHUNK)   bload(c + 1, 0, nxt);
            const uint4 Bh0 = Breg[cur][0], Bh1 = Breg[cur][1];
            const uint4 Bl0 = Breg[cur][2], Bl1 = Breg[cur][3];
            #pragma unroll
            for (int m = 0; m < 2; ++m) {
                uint32_t ah0, ah1, ah2, ah3, al0, al1, al2, al3;
                ldsm4(ah0, ah1, ah2, ah3, abase + (0 * 4 + s) * 1024 + m * 512 + laddr);
                ldsm4(al0, al1, al2, al3, abase + (4 + s) * 1024 + m * 512 + laddr);
                mma16816(acc[m][0], ah0, ah1, ah2, ah3, Bh0.x, Bh0.y);
                mma16816(acc[m][1], ah0, ah1, ah2, ah3, Bh0.z, Bh0.w);
                mma16816(acc[m][2], ah0, ah1, ah2, ah3, Bh1.x, Bh1.y);
                mma16816(acc[m][3], ah0, ah1, ah2, ah3, Bh1.z, Bh1.w);
                mma16816(acc[m][0], ah0, ah1, ah2, ah3, Bl0.x, Bl0.y);
                mma16816(acc[m][1], ah0, ah1, ah2, ah3, Bl0.z, Bl0.w);
                mma16816(acc[m][2], ah0, ah1, ah2, ah3, Bl1.x, Bl1.y);
                mma16816(acc[m][3], ah0, ah1, ah2, ah3, Bl1.z, Bl1.w);
                mma16816(acc[m][0], al0, al1, al2, al3, Bh0.x, Bh0.y);
                mma16816(acc[m][1], al0, al1, al2, al3, Bh0.z, Bh0.w);
                mma16816(acc[m][2], al0, al1, al2, al3, Bh1.x, Bh1.y);
                mma16816(acc[m][3], al0, al1, al2, al3, Bh1.z, Bh1.w);
            }
        }
    };

    // ---- prologue ----
    load_idx(0, 0);
    load_idx(1, 1);
    load_idx(2, 2);
    bload(0, 0, 0);                  // first B tile in flight early
    table_ldg(0);
    table_ldg(1);
    cv_store(0);
    pair_bar(p + 1);

    // ---- free-running pipelined loop (pair-local sync only) ----
    #pragma unroll
    for (int c = 0; c < NCHUNK; ++c) {
        if (c + 3 < NCHUNK) load_idx(c + 3, (c + 3) % 3);
        if (c + 2 < NCHUNK) table_ldg(c + 2);
        do_mma(c);
        if (c + 1 < NCHUNK) cv_store(c + 1);
        if (c + 1 < NCHUNK) pair_bar(p + 1);
    }
    __syncthreads();

    // ---- epilogue (aliases A region) ----
    float* sFO = (float*)(smem + EXP_FO);
    float* sS  = (float*)(smem + EXP_S);
    float* sM  = (float*)(smem + EXP_M);
    float* sH  = (float*)(smem + EXP_H);

    {
        float* dst = nh ? sS : sFO;
        #pragma unroll
        for (int m = 0; m < 2; ++m) {
            const int r0 = p * 32 + m * 16 + (l >> 2);
            const int r1 = r0 + 8;
            #pragma unroll
            for (int t = 0; t < 4; ++t) {
                const int c0 = t * 8 + (l & 3) * 2;
                dst[r0 * 33 + c0]     = acc[m][t][0];
                dst[r0 * 33 + c0 + 1] = acc[m][t][1];
                dst[r1 * 33 + c0]     = acc[m][t][2];
                dst[r1 * 33 + c0 + 1] = acc[m][t][3];
            }
        }
    }
    for (int i = tid; i < 1024; i += THREADS) {
        sM[i]        = lin1_w[i];
        sM[1056 + i] = lin2_w[i];
    }
    if (tid < 32) {
        sM[1024 + tid] = lin1_b[tid];
        sM[2080 + tid] = lin2_b[tid];
        sM[2112 + tid] = last_w[tid];
    }
    if (tid == 0) sM[2144] = last_b[0];
    __syncthreads();

    // ---- MLP: 2 threads per row, 16 outputs each ----
    const int mrow = tid >> 1;
    const int mh   = tid & 1;

    float xr[32];
    #pragma unroll
    for (int j = 0; j < 32; ++j) {
        float s = sS[mrow * 33 + j];
        xr[j] = fmaf(s, s, sFO[mrow * 33 + j]);
    }
    #pragma unroll
    for (int i = 0; i < 16; ++i) {
        int oi = mh * 16 + i;
        float t = sM[1024 + oi];
        #pragma unroll
        for (int j4 = 0; j4 < 8; ++j4) {
            float4 w = *(const float4*)&sM[oi * 32 + j4 * 4];
            t = fmaf(xr[j4 * 4],     w.x, t);
            t = fmaf(xr[j4 * 4 + 1], w.y, t);
            t = fmaf(xr[j4 * 4 + 2], w.z, t);
            t = fmaf(xr[j4 * 4 + 3], w.w, t);
        }
        sH[mrow * 33 + oi] = fmaxf(t, 0.f);
    }
    __syncthreads();

    float hr[32];
    #pragma unroll
    for (int j = 0; j < 32; ++j) hr[j] = sH[mrow * 33 + j];
    #pragma unroll
    for (int i = 0; i < 16; ++i) {
        int oi = mh * 16 + i;
        float t = sM[2080 + oi];
        #pragma unroll
        for (int j4 = 0; j4 < 8; ++j4) {
            float4 w = *(const float4*)&sM[1056 + oi * 32 + j4 * 4];
            t = fmaf(hr[j4 * 4],     w.x, t);
            t = fmaf(hr[j4 * 4 + 1], w.y, t);
            t = fmaf(hr[j4 * 4 + 2], w.z, t);
            t = fmaf(hr[j4 * 4 + 3], w.w, t);
        }
        sFO[mrow * 33 + oi] = fmaxf(t, 0.f);   // reuse sFO for h2
    }
    __syncthreads();

    if (mh == 0) {
        float o = sM[2144];
        #pragma unroll
        for (int j = 0; j < 32; ++j) o = fmaf(sFO[mrow * 33 + j], sM[2112 + j], o);
        out[b0 + mrow] = o;
    }
}

extern "C" void kernel_launch(void* const* d_in, const int* in_sizes, int n_in,
                              void* d_out, int out_size) {
    const int*   Xi     = (const int*)  d_in[0];
    const float* Xv     = (const float*)d_in[1];
    const float* tables = (const float*)d_in[2];
    const float* W1     = (const float*)d_in[3];
    const float* Wi     = (const float*)d_in[4];
    const float* lin1_w = (const float*)d_in[5];
    const float* lin1_b = (const float*)d_in[6];
    const float* lin2_w = (const float*)d_in[7];
    const float* lin2_b = (const float*)d_in[8];
    const float* last_w = (const float*)d_in[9];
    const float* last_b = (const float*)d_in[10];
    float* out = (float*)d_out;

    static bool attr_set = false;
    if (!attr_set) {
        cudaFuncSetAttribute(pnn_kernel, cudaFuncAttributeMaxDynamicSharedMemorySize, SMEM_BYTES);
        attr_set = true;
    }

    prep_kernel<<<(10 * 2 * 4 * 4 * 32 * 4 + 255) / 256, 256>>>(W1, Wi);
    pnn_kernel<<<BATCH / ROWSPB, THREADS, SMEM_BYTES>>>(
        Xi, Xv, tables, lin1_w, lin1_b, lin2_w, lin2_b, last_w, last_b, out);
}